// round 16
// baseline (speedup 1.0000x reference)
#include <cuda_runtime.h>
#include <math.h>

// DistinctionLoss: two-kernel version with TMA (cp.async.bulk) smem staging.
// features [8,4096,256] f32, scores [8,4096,1] f32 -> scalar f32.
//
// mean(gram) = sum_b ||s_b||^2 / (B*N^2), s_b = sum_n unit(features[b,n,:]).
// Register-starved LDG batching kept getting serialized by ptxas (regs pinned
// at 32-40 across rounds -> ~2 TB/s). cp.async.bulk moves the MLP into the
// TMA engine: one 32KB bulk copy per block, compute from smem.
// Kernel 1: stage rows -> norms -> s_b partials (8 accumulation groups).
// Kernel 2: stage rows -> reconstruct s_b (overlapped with TMA) -> dots ->
//           BCE tail; last block (ticket) finalizes + resets state.

#define BB 8
#define NN 4096
#define DD 256
#define NTHREADS 256
#define NWARPS 8
#define ROWS_PER_BLOCK 32
#define NBLK ((BB * NN) / ROWS_PER_BLOCK)        // 1024
#define ROWS_PER_WARP (ROWS_PER_BLOCK / NWARPS)  // 4
#define NGRP 8
#define TILE_BYTES (ROWS_PER_BLOCK * DD * 4)     // 32768

// Persistent scratch; zero-initialized at module load, self-reset each launch.
__device__ float  g_rnorm[BB * NN];
__device__ float  g_part[NGRP * BB * DD];        // s_b partials, 8 groups
__device__ double g_bce;
__device__ unsigned int g_ticket;

__device__ __forceinline__ unsigned int smem_u32(const void* p) {
    unsigned int a;
    asm("{ .reg .u64 t; cvta.to.shared.u64 t, %1; cvt.u32.u64 %0, t; }"
        : "=r"(a) : "l"(p));
    return a;
}
__device__ __forceinline__ void mbar_init(unsigned int a, unsigned int cnt) {
    asm volatile("mbarrier.init.shared.b64 [%0], %1;" :: "r"(a), "r"(cnt) : "memory");
}
__device__ __forceinline__ void mbar_expect(unsigned int a, unsigned int bytes) {
    asm volatile("mbarrier.arrive.expect_tx.shared.b64 _, [%0], %1;"
                 :: "r"(a), "r"(bytes) : "memory");
}
__device__ __forceinline__ void bulk_g2s(unsigned int dst, const void* src,
                                         unsigned int bytes, unsigned int mbar) {
    asm volatile("cp.async.bulk.shared::cluster.global.mbarrier::complete_tx::bytes "
                 "[%0], [%1], %2, [%3];"
                 :: "r"(dst), "l"(src), "r"(bytes), "r"(mbar) : "memory");
}
__device__ __forceinline__ void mbar_wait(unsigned int a, unsigned int par) {
    asm volatile("{\n\t.reg .pred p;\n\t"
                 "WAITLP_%=:\n\t"
                 "mbarrier.try_wait.parity.acquire.cta.shared::cta.b64 p, [%0], %1;\n\t"
                 "@!p bra WAITLP_%=;\n\t}"
                 :: "r"(a), "r"(par) : "memory");
}

// ---------------- Kernel 1: stage -> norms -> s_b group partials ----------
__global__ void __launch_bounds__(NTHREADS) pass1_kernel(const float* __restrict__ feat) {
    __shared__ __align__(128) float tile[ROWS_PER_BLOCK * DD];   // 32KB
    __shared__ float s_acc[DD];
    __shared__ unsigned long long mbar;

    int tid  = threadIdx.x;
    int wid  = tid >> 5;
    int lane = tid & 31;
    int rowBase = blockIdx.x * ROWS_PER_BLOCK;
    int b       = rowBase >> 12;                 // / NN

    unsigned int mb = smem_u32(&mbar);
    s_acc[tid] = 0.0f;
    if (tid == 0) mbar_init(mb, 1);
    __syncthreads();
    if (tid == 0) {
        mbar_expect(mb, TILE_BYTES);
        bulk_g2s(smem_u32(tile), feat + (size_t)rowBase * DD, TILE_BYTES, mb);
    }
    mbar_wait(mb, 0);

    const float4* t4 = (const float4*)tile;
    float4 acc0 = make_float4(0.f, 0.f, 0.f, 0.f);
    float4 acc1 = make_float4(0.f, 0.f, 0.f, 0.f);

    // 4 rows per warp, interleaved reduction chains.
    float4 a0[ROWS_PER_WARP], a1[ROWS_PER_WARP];
    float  ss[ROWS_PER_WARP];
    #pragma unroll
    for (int r = 0; r < ROWS_PER_WARP; r++) {
        int rl = wid * ROWS_PER_WARP + r;
        a0[r] = t4[rl * 64 + lane];
        a1[r] = t4[rl * 64 + 32 + lane];
    }
    #pragma unroll
    for (int r = 0; r < ROWS_PER_WARP; r++)
        ss[r] = a0[r].x*a0[r].x + a0[r].y*a0[r].y + a0[r].z*a0[r].z + a0[r].w*a0[r].w
              + a1[r].x*a1[r].x + a1[r].y*a1[r].y + a1[r].z*a1[r].z + a1[r].w*a1[r].w;
    #pragma unroll
    for (int o = 16; o > 0; o >>= 1) {
        #pragma unroll
        for (int r = 0; r < ROWS_PER_WARP; r++)
            ss[r] += __shfl_xor_sync(0xffffffffu, ss[r], o);
    }
    #pragma unroll
    for (int r = 0; r < ROWS_PER_WARP; r++) {
        float rn = rsqrtf(fmaxf(ss[r], 1e-24f));
        int rl = wid * ROWS_PER_WARP + r;
        if (lane == 0) g_rnorm[rowBase + rl] = rn;
        acc0.x += a0[r].x * rn; acc0.y += a0[r].y * rn;
        acc0.z += a0[r].z * rn; acc0.w += a0[r].w * rn;
        acc1.x += a1[r].x * rn; acc1.y += a1[r].y * rn;
        acc1.z += a1[r].z * rn; acc1.w += a1[r].w * rn;
    }

    int d0 = lane * 4;
    atomicAdd(&s_acc[d0 + 0],       acc0.x);
    atomicAdd(&s_acc[d0 + 1],       acc0.y);
    atomicAdd(&s_acc[d0 + 2],       acc0.z);
    atomicAdd(&s_acc[d0 + 3],       acc0.w);
    atomicAdd(&s_acc[128 + d0 + 0], acc1.x);
    atomicAdd(&s_acc[128 + d0 + 1], acc1.y);
    atomicAdd(&s_acc[128 + d0 + 2], acc1.z);
    atomicAdd(&s_acc[128 + d0 + 3], acc1.w);
    __syncthreads();

    int grp = blockIdx.x & (NGRP - 1);
    atomicAdd(&g_part[(grp * BB + b) * DD + tid], s_acc[tid]);
}

// ------ Kernel 2: stage -> s_b reconstruct -> dots -> BCE -> finalize ------
__global__ void __launch_bounds__(NTHREADS) pass2_kernel(const float* __restrict__ feat,
                                                         const float* __restrict__ scores,
                                                         float* __restrict__ out) {
    __shared__ __align__(128) float tile[ROWS_PER_BLOCK * DD];   // 32KB
    __shared__ float s_fs[ROWS_PER_BLOCK];
    __shared__ float s_red[NWARPS];
    __shared__ unsigned long long mbar;
    __shared__ unsigned int s_am_last;

    int tid  = threadIdx.x;
    int wid  = tid >> 5;
    int lane = tid & 31;
    int rowBase = blockIdx.x * ROWS_PER_BLOCK;
    int b       = rowBase >> 12;

    unsigned int mb = smem_u32(&mbar);
    if (tid == 0) mbar_init(mb, 1);
    __syncthreads();
    if (tid == 0) {
        mbar_expect(mb, TILE_BYTES);
        bulk_g2s(smem_u32(tile), feat + (size_t)rowBase * DD, TILE_BYTES, mb);
    }

    // Reconstruct s_b from the 8 group partials WHILE the TMA flies.
    float4 s0 = make_float4(0.f, 0.f, 0.f, 0.f);
    float4 s1 = make_float4(0.f, 0.f, 0.f, 0.f);
    #pragma unroll
    for (int g = 0; g < NGRP; g++) {
        const float4* p4 = (const float4*)(g_part + (g * BB + b) * DD);
        float4 u = __ldcg(&p4[lane]);
        float4 v = __ldcg(&p4[lane + 32]);
        s0.x += u.x; s0.y += u.y; s0.z += u.z; s0.w += u.w;
        s1.x += v.x; s1.y += v.y; s1.z += v.z; s1.w += v.w;
    }

    mbar_wait(mb, 0);

    const float4* t4 = (const float4*)tile;
    float dt[ROWS_PER_WARP];
    {
        float4 a0[ROWS_PER_WARP], a1[ROWS_PER_WARP];
        #pragma unroll
        for (int r = 0; r < ROWS_PER_WARP; r++) {
            int rl = wid * ROWS_PER_WARP + r;
            a0[r] = t4[rl * 64 + lane];
            a1[r] = t4[rl * 64 + 32 + lane];
        }
        #pragma unroll
        for (int r = 0; r < ROWS_PER_WARP; r++)
            dt[r] = a0[r].x*s0.x + a0[r].y*s0.y + a0[r].z*s0.z + a0[r].w*s0.w
                  + a1[r].x*s1.x + a1[r].y*s1.y + a1[r].z*s1.z + a1[r].w*s1.w;
    }
    #pragma unroll
    for (int o = 16; o > 0; o >>= 1) {
        #pragma unroll
        for (int r = 0; r < ROWS_PER_WARP; r++)
            dt[r] += __shfl_xor_sync(0xffffffffu, dt[r], o);
    }
    if (lane == 0) {
        #pragma unroll
        for (int r = 0; r < ROWS_PER_WARP; r++)
            s_fs[wid * ROWS_PER_WARP + r] = dt[r];
    }
    __syncthreads();

    // ---- BCE tail: one thread per row (warp 0) ----
    float local = 0.0f;
    if (tid < ROWS_PER_BLOCK) {
        int row   = rowBase + tid;
        float fs  = s_fs[tid] * g_rnorm[row];
        float sim = (fs - 1.0f) * (1.0f / (float)(NN - 1));
        float t   = 1.0f - fmaxf(sim, 0.0f);
        float sc  = scores[row];
        float ls  = fmaxf(__logf(sc),        -100.0f);
        float l1  = fmaxf(__logf(1.0f - sc), -100.0f);
        local = -(t * ls + (1.0f - t) * l1);
    }
    if (wid == 0) {
        #pragma unroll
        for (int o = 16; o > 0; o >>= 1)
            local += __shfl_xor_sync(0xffffffffu, local, o);
        if (lane == 0) {
            atomicAdd(&g_bce, (double)local);
            __threadfence();                           // publish before ticket
            s_am_last = (atomicAdd(&g_ticket, 1u) == NBLK - 1);
        }
    }
    __syncthreads();
    if (!s_am_last) return;

    // ---- Last block: all NBLK BCE atomics visible. Finalize. ----
    __threadfence();                                   // acquire side
    float ssq = 0.0f;
    #pragma unroll
    for (int i = 0; i < (BB * DD) / NTHREADS; i++) {   // 8 elements per thread
        int e = tid + i * NTHREADS;
        float v = 0.0f;
        #pragma unroll
        for (int g = 0; g < NGRP; g++)
            v += __ldcg(&g_part[g * BB * DD + e]);
        ssq += v * v;
    }
    #pragma unroll
    for (int o = 16; o > 0; o >>= 1)
        ssq += __shfl_xor_sync(0xffffffffu, ssq, o);
    if (lane == 0) s_red[wid] = ssq;
    __syncthreads();
    if (wid == 0) {
        float t2 = (lane < NWARPS) ? s_red[lane] : 0.0f;
        #pragma unroll
        for (int o = 4; o > 0; o >>= 1)
            t2 += __shfl_xor_sync(0xffffffffu, t2, o);
        if (lane == 0) {
            double bce       = atomicAdd(&g_bce, 0.0) / (double)(BB * NN);
            double mean_gram = (double)t2 /
                               ((double)BB * (double)NN * (double)NN);
            out[0] = (float)(bce + (1.0 - mean_gram));
            g_bce    = 0.0;                            // reset for next launch
            g_ticket = 0u;
        }
    }
    __syncthreads();                                   // all reads of g_part done
    #pragma unroll
    for (int i = 0; i < (NGRP * BB * DD) / NTHREADS; i++)
        g_part[tid + i * NTHREADS] = 0.0f;             // reset for next launch
}

extern "C" void kernel_launch(void* const* d_in, const int* in_sizes, int n_in,
                              void* d_out, int out_size) {
    const float* feat   = (const float*)d_in[0];
    const float* scores = (const float*)d_in[1];
    float* out = (float*)d_out;

    pass1_kernel<<<NBLK, NTHREADS>>>(feat);
    pass2_kernel<<<NBLK, NTHREADS>>>(feat, scores, out);
}

// round 17
// speedup vs baseline: 1.5503x; 1.5503x over previous
#include <cuda_runtime.h>
#include <math.h>

// DistinctionLoss: two-kernel version (R12 structure) with asm-forced MLP.
// features [8,4096,256] f32, scores [8,4096,1] f32 -> scalar f32.
//
// mean(gram) = sum_b ||s_b||^2 / (B*N^2), s_b = sum_n unit(features[b,n,:]).
// ptxas's remat heuristic kept sinking batched loads to uses (regs pinned at
// 32-47 every round -> effective MLP ~2 -> ~2 TB/s). asm volatile loads cannot
// be sunk or reordered, forcing 8 LDG.128 in flight per warp.

#define BB 8
#define NN 4096
#define DD 256
#define NBLK 512
#define NTHREADS 256
#define NWARPS (NTHREADS / 32)                   // 8
#define ROWS_PER_BLOCK ((BB * NN) / NBLK)        // 64
#define ROWS_PER_WARP  (ROWS_PER_BLOCK / NWARPS) // 8
#define RBATCH 4

// Persistent scratch; zero-initialized at module load, self-reset each launch.
__device__ float  g_rnorm[BB * NN];
__device__ float  g_s[BB * DD];
__device__ double g_bce;
__device__ unsigned int g_ticket;

// Batched un-sinkable 128-bit load.
__device__ __forceinline__ void ldg128(float4& v, const float4* p) {
    asm volatile("ld.global.v4.f32 {%0,%1,%2,%3}, [%4];"
                 : "=f"(v.x), "=f"(v.y), "=f"(v.z), "=f"(v.w)
                 : "l"(p));
}

// ---------------- Kernel 1: row norms + s_b accumulation ----------------
__global__ void __launch_bounds__(NTHREADS) pass1_kernel(const float* __restrict__ feat) {
    __shared__ float s_acc[DD];
    int tid  = threadIdx.x;
    int wid  = tid >> 5;
    int lane = tid & 31;
    s_acc[tid] = 0.0f;
    __syncthreads();

    int rowBase = blockIdx.x * ROWS_PER_BLOCK;   // 64 | 4096 -> single batch
    int b       = rowBase >> 12;
    int row0    = rowBase + wid * ROWS_PER_WARP;

    float4 acc0 = make_float4(0.f, 0.f, 0.f, 0.f);
    float4 acc1 = make_float4(0.f, 0.f, 0.f, 0.f);

    #pragma unroll
    for (int rb = 0; rb < ROWS_PER_WARP; rb += RBATCH) {
        float4 a0[RBATCH], a1[RBATCH];
        // 8 back-to-back LDG.128 - asm volatile cannot be sunk by ptxas.
        #pragma unroll
        for (int r = 0; r < RBATCH; r++) {
            const float4* p = (const float4*)(feat + (size_t)(row0 + rb + r) * DD);
            ldg128(a0[r], p + lane);
            ldg128(a1[r], p + lane + 32);
        }
        float ss[RBATCH];
        #pragma unroll
        for (int r = 0; r < RBATCH; r++)
            ss[r] = a0[r].x*a0[r].x + a0[r].y*a0[r].y + a0[r].z*a0[r].z + a0[r].w*a0[r].w
                  + a1[r].x*a1[r].x + a1[r].y*a1[r].y + a1[r].z*a1[r].z + a1[r].w*a1[r].w;
        #pragma unroll
        for (int o = 16; o > 0; o >>= 1) {        // interleaved butterflies
            #pragma unroll
            for (int r = 0; r < RBATCH; r++)
                ss[r] += __shfl_xor_sync(0xffffffffu, ss[r], o);
        }
        #pragma unroll
        for (int r = 0; r < RBATCH; r++) {
            float rn = rsqrtf(fmaxf(ss[r], 1e-24f));
            if (lane == 0) g_rnorm[row0 + rb + r] = rn;
            acc0.x += a0[r].x * rn; acc0.y += a0[r].y * rn;
            acc0.z += a0[r].z * rn; acc0.w += a0[r].w * rn;
            acc1.x += a1[r].x * rn; acc1.y += a1[r].y * rn;
            acc1.z += a1[r].z * rn; acc1.w += a1[r].w * rn;
        }
    }

    int d0 = lane * 4;
    atomicAdd(&s_acc[d0 + 0],       acc0.x);
    atomicAdd(&s_acc[d0 + 1],       acc0.y);
    atomicAdd(&s_acc[d0 + 2],       acc0.z);
    atomicAdd(&s_acc[d0 + 3],       acc0.w);
    atomicAdd(&s_acc[128 + d0 + 0], acc1.x);
    atomicAdd(&s_acc[128 + d0 + 1], acc1.y);
    atomicAdd(&s_acc[128 + d0 + 2], acc1.z);
    atomicAdd(&s_acc[128 + d0 + 3], acc1.w);
    __syncthreads();

    atomicAdd(&g_s[b * DD + tid], s_acc[tid]);
}

// -------- Kernel 2: streaming dots -> parallel BCE tail -> finalize --------
__global__ void __launch_bounds__(NTHREADS) pass2_kernel(const float* __restrict__ feat,
                                                         const float* __restrict__ scores,
                                                         float* __restrict__ out) {
    __shared__ float s_fs[ROWS_PER_BLOCK];       // raw dot per row
    __shared__ float s_red[NWARPS];
    int tid  = threadIdx.x;
    int wid  = tid >> 5;
    int lane = tid & 31;

    int rowBase = blockIdx.x * ROWS_PER_BLOCK;
    int b       = rowBase >> 12;
    int row0    = rowBase + wid * ROWS_PER_WARP;

    // Lane-mapped s_b slices (atomics from pass1 landed in L2).
    const float4* gs4 = (const float4*)(g_s + b * DD);
    float4 s0 = __ldcg(&gs4[lane]);
    float4 s1 = __ldcg(&gs4[lane + 32]);

    #pragma unroll
    for (int rb = 0; rb < ROWS_PER_WARP; rb += RBATCH) {
        float4 a0[RBATCH], a1[RBATCH];
        // 8 back-to-back LDG.128 - asm volatile cannot be sunk by ptxas.
        #pragma unroll
        for (int r = 0; r < RBATCH; r++) {
            const float4* p = (const float4*)(feat + (size_t)(row0 + rb + r) * DD);
            ldg128(a0[r], p + lane);
            ldg128(a1[r], p + lane + 32);
        }
        float dt[RBATCH];
        #pragma unroll
        for (int r = 0; r < RBATCH; r++)
            dt[r] = a0[r].x*s0.x + a0[r].y*s0.y + a0[r].z*s0.z + a0[r].w*s0.w
                  + a1[r].x*s1.x + a1[r].y*s1.y + a1[r].z*s1.z + a1[r].w*s1.w;
        #pragma unroll
        for (int o = 16; o > 0; o >>= 1) {        // interleaved butterflies
            #pragma unroll
            for (int r = 0; r < RBATCH; r++)
                dt[r] += __shfl_xor_sync(0xffffffffu, dt[r], o);
        }
        if (lane == 0) {
            #pragma unroll
            for (int r = 0; r < RBATCH; r++)
                s_fs[wid * ROWS_PER_WARP + rb + r] = dt[r];
        }
    }
    __syncthreads();

    // ---- 64-wide BCE tail (one thread per row) ----
    float local = 0.0f;
    if (tid < ROWS_PER_BLOCK) {
        int row   = rowBase + tid;
        float fs  = s_fs[tid] * g_rnorm[row];
        float sim = (fs - 1.0f) * (1.0f / (float)(NN - 1));
        float t   = 1.0f - fmaxf(sim, 0.0f);
        float sc  = scores[row];
        float ls  = fmaxf(__logf(sc),        -100.0f);
        float l1  = fmaxf(__logf(1.0f - sc), -100.0f);
        local = -(t * ls + (1.0f - t) * l1);
    }
    #pragma unroll
    for (int o = 16; o > 0; o >>= 1)
        local += __shfl_xor_sync(0xffffffffu, local, o);
    if (lane == 0) s_red[wid] = local;
    __syncthreads();

    __shared__ unsigned int s_am_last;
    if (tid == 0) {
        atomicAdd(&g_bce, (double)(s_red[0] + s_red[1]));
        __threadfence();                               // publish before ticket
        s_am_last = (atomicAdd(&g_ticket, 1u) == NBLK - 1);
    }
    __syncthreads();
    if (!s_am_last) return;

    // ---- Last block: all NBLK BCE atomics are visible. Finalize. ----
    __threadfence();                                   // acquire side
    float ss = 0.0f;
    #pragma unroll
    for (int i = 0; i < (BB * DD) / NTHREADS; i++) {
        float v = __ldcg(&g_s[tid + i * NTHREADS]);
        ss += v * v;
    }
    #pragma unroll
    for (int o = 16; o > 0; o >>= 1)
        ss += __shfl_xor_sync(0xffffffffu, ss, o);
    if (lane == 0) s_red[wid] = ss;
    __syncthreads();
    if (wid == 0) {
        float t2 = (lane < NWARPS) ? s_red[lane] : 0.0f;
        #pragma unroll
        for (int o = 4; o > 0; o >>= 1)
            t2 += __shfl_xor_sync(0xffffffffu, t2, o);
        if (lane == 0) {
            double bce       = atomicAdd(&g_bce, 0.0) / (double)(BB * NN);
            double mean_gram = (double)t2 /
                               ((double)BB * (double)NN * (double)NN);
            out[0] = (float)(bce + (1.0 - mean_gram));
            g_bce    = 0.0;                            // reset for next launch
            g_ticket = 0u;
        }
    }
    __syncthreads();                                   // all reads of g_s done
    #pragma unroll
    for (int i = 0; i < (BB * DD) / NTHREADS; i++)
        g_s[tid + i * NTHREADS] = 0.0f;                // reset for next launch
}

extern "C" void kernel_launch(void* const* d_in, const int* in_sizes, int n_in,
                              void* d_out, int out_size) {
    const float* feat   = (const float*)d_in[0];
    const float* scores = (const float*)d_in[1];
    float* out = (float*)d_out;

    pass1_kernel<<<NBLK, NTHREADS>>>(feat);
    pass2_kernel<<<NBLK, NTHREADS>>>(feat, scores, out);
}